// round 7
// baseline (speedup 1.0000x reference)
#include <cuda_runtime.h>

typedef unsigned long long u64;
typedef unsigned int u32;

#define BATCH 16
#define NPRI  3000
#define NCLS  201
#define CM1   200
#define NCAND (NPRI * CM1)
#define TOPN  100
#define SCORE_THRESH 0.02f
#define NMS_THRESH   0.45f
#define CAP     20480
#define COMPCAP 1024
#define NTHR    1024
#define MARK    0x8000000000000000ULL

/* ---- static device scratch (zero-init at load; nms restores zeros) ---- */
__device__ u64    g_keys[(long)BATCH * NCAND];
__device__ int    g_count[BATCH];
__device__ u32    g_maxbits[BATCH];   /* max fenc(coord)          */
__device__ u32    g_minbits[BATCH];   /* max fenc(-coord) => min  */
__device__ float4 g_decoded[BATCH * NPRI];

__device__ __forceinline__ u64 umax64(u64 a, u64 b) { return a > b ? a : b; }

__device__ __forceinline__ unsigned fenc(float f) {
    unsigned u = __float_as_uint(f);
    return (u & 0x80000000u) ? ~u : (u | 0x80000000u);
}
__device__ __forceinline__ float fdec(unsigned e) {
    unsigned u = (e & 0x80000000u) ? (e & 0x7fffffffu) : ~e;
    return __uint_as_float(u);
}

/* warp max of u64 via 2x 32-bit REDUX (low word = ~flat_idx => tie->smallest idx) */
__device__ __forceinline__ u64 wmax64(u64 k) {
    u32 hi = (u32)(k >> 32);
    u32 mh = __reduce_max_sync(0xffffffffu, hi);
    u32 ml = __reduce_max_sync(0xffffffffu, (hi == mh) ? (u32)k : 0u);
    return ((u64)mh << 32) | ml;
}

/* score (positive float bits) -> 256-bin monotone bucket over (0.02, 1.0] */
__device__ __forceinline__ int score_bin(u32 khi) {
    int v = (int)(khi >> 18) - 3880;     /* 0x3CA3D70A>>18 = 3880 */
    return v < 0 ? 0 : (v > 255 ? 255 : v);
}

/* grid (NPRI/8, BATCH), block 256: one warp per (image, prior) row */
__global__ void stage_a(const float* __restrict__ deltas,
                        const float* __restrict__ obj,
                        const float* __restrict__ priors) {
    const int lane = threadIdx.x & 31;
    const int wid  = threadIdx.x >> 5;
    const int p    = blockIdx.x * 8 + wid;
    const int b    = blockIdx.y;
    const long row = (long)b * NPRI + p;
    const float* o = obj + row * NCLS;

    __shared__ int s_cnt, s_off;
    if (threadIdx.x == 0) s_cnt = 0;
    __syncthreads();

    /* softmax over 201 classes */
    float v[7];
    float m = -3.4e38f;
#pragma unroll
    for (int k = 0; k < 7; k++) {
        int c = lane + 32 * k;
        v[k] = (c < NCLS) ? o[c] : -3.4e38f;
        m = fmaxf(m, v[k]);
    }
#pragma unroll
    for (int d = 16; d; d >>= 1) m = fmaxf(m, __shfl_xor_sync(0xffffffffu, m, d));
    float e[7]; float sum = 0.f;
#pragma unroll
    for (int k = 0; k < 7; k++) {
        int c = lane + 32 * k;
        e[k] = (c < NCLS) ? expf(v[k] - m) : 0.f;
        sum += e[k];
    }
#pragma unroll
    for (int d = 16; d; d >>= 1) sum += __shfl_xor_sync(0xffffffffu, sum, d);

    /* prefilter (no false negatives), exact divide only for ~3% of elems */
    const float pre = 0.0195f * sum;
    float prob[7]; int pass[7]; int cnt = 0;
#pragma unroll
    for (int k = 0; k < 7; k++) {
        int c = lane + 32 * k;
        pass[k] = 0;
        if (c >= 1 && c < NCLS && e[k] > pre) {
            float pv = __fdiv_rn(e[k], sum);
            if (pv > SCORE_THRESH) { pass[k] = 1; prob[k] = pv; }
        }
        cnt += pass[k];
    }
    int inc = cnt;
#pragma unroll
    for (int d = 1; d < 32; d <<= 1) {
        int t = __shfl_up_sync(0xffffffffu, inc, d);
        if (lane >= d) inc += t;
    }
    int total = __shfl_sync(0xffffffffu, inc, 31);
    int excl  = inc - cnt;

    /* two-level offset: warp -> block(shared) -> one global atomic per block */
    int wbase = 0;
    if (lane == 0 && total > 0) wbase = atomicAdd(&s_cnt, total);
    wbase = __shfl_sync(0xffffffffu, wbase, 0);
    __syncthreads();
    if (threadIdx.x == 0) s_off = s_cnt ? atomicAdd(&g_count[b], s_cnt) : 0;
    __syncthreads();

    u64* kd = g_keys + (long)b * NCAND;
    int w = s_off + wbase + excl;
#pragma unroll
    for (int k = 0; k < 7; k++) {
        if (pass[k]) {
            int c = lane + 32 * k;
            u32 pk = ((u32)p << 8) | (u32)(c - 1);
            kd[w] = ((u64)__float_as_uint(prob[k]) << 32) | (u32)(~pk);
            w++;
        }
    }

    /* box decode + per-image coord max/min (lane 0, vectorized loads) */
    if (lane == 0) {
        float4 dl = ((const float4*)deltas)[row];
        float4 pr = ((const float4*)priors)[p];
        float pw = pr.z, ph = pr.w;
        float cx = dl.x * 0.1f * pw + pr.x;
        float cy = dl.y * 0.1f * ph + pr.y;
        float bw = expf(dl.z * 0.2f) * pw;
        float bh = expf(dl.w * 0.2f) * ph;
        float x1 = cx - 0.5f * bw, y1 = cy - 0.5f * bh;
        float x2 = cx + 0.5f * bw, y2 = cy + 0.5f * bh;
        g_decoded[row] = make_float4(x1, y1, x2, y2);
        float mm = fmaxf(fmaxf(x1, y1), fmaxf(x2, y2));
        float mn = fminf(fminf(x1, y1), fminf(x2, y2));
        atomicMax(&g_maxbits[b], fenc(mm));
        atomicMax(&g_minbits[b], fenc(-mn));
    }
}

struct Sm {
    float4 sbox[NPRI];        /* 48 KB decoded boxes */
    u64    keys[CAP];         /* label-grouped candidate keys */
    u64    comp[COMPCAP];     /* compacted top candidates */
    u64    red[32];
    int    hist[256];
    int    seg[CM1 + 1];
    int    cnt[CM1];
    int    cur[CM1];
    int    misc[8];           /* 0:T 2:M 3:total */
    float  fbc[8];
    int    flag;
};

__global__ void __launch_bounds__(NTHR) nms_kernel(float* __restrict__ out) {
    extern __shared__ char smraw[];
    Sm* sm = (Sm*)smraw;
    const int b   = blockIdx.x;
    const int tid = threadIdx.x;
    const int wid = tid >> 5, lane = tid & 31;

    const int   n    = g_count[b];
    const float off  = fdec(g_maxbits[b]) + 1.0f;
    const float minv = -fdec(g_minbits[b]);
    const bool  fast = (n <= CAP) && (minv > -1.0f);

    /* pre-zero output rows for this image */
    for (int q = tid; q < TOPN * 6; q += NTHR) out[(long)b * TOPN * 6 + q] = 0.f;

    for (int i = tid; i < NPRI; i += NTHR)
        sm->sbox[i] = g_decoded[b * NPRI + i];

    if (fast) {
        for (int l = tid; l < CM1; l += NTHR) { sm->cnt[l] = 0; sm->cur[l] = 0; }
        if (tid < 256) sm->hist[tid] = 0;
        if (tid < 8)   sm->misc[tid] = 0;
        __syncthreads();

        /* label histogram from keys */
        const u64* gk = g_keys + (long)b * NCAND;
        for (int j = tid; j < n; j += NTHR) {
            int labf = (int)((~(u32)gk[j]) & 255u);
            atomicAdd(&sm->cnt[labf], 1);
        }
        __syncthreads();

        /* warp 0: exclusive prefix over 200 bins */
        if (wid == 0) {
            int carry = 0;
#pragma unroll
            for (int c = 0; c < 7; c++) {
                int l = c * 32 + lane;
                int h = (l < CM1) ? sm->cnt[l] : 0;
                int v = h;
#pragma unroll
                for (int d = 1; d < 32; d <<= 1) {
                    int t = __shfl_up_sync(0xffffffffu, v, d);
                    if (lane >= d) v += t;
                }
                if (l < CM1) sm->seg[l] = carry + v - h;
                carry += __shfl_sync(0xffffffffu, v, 31);
            }
            if (lane == 0) sm->seg[CM1] = carry;
        }
        __syncthreads();

        /* scatter by label */
        for (int j = tid; j < n; j += NTHR) {
            u64 k = gk[j];
            int labf = (int)((~(u32)k) & 255u);
            int pos  = sm->seg[labf] + atomicAdd(&sm->cur[labf], 1);
            sm->keys[pos] = k;
        }
        __syncthreads();

        /* ---- per-label greedy NMS, one label per warp, fully parallel ---- */
        for (int l = wid; l < CM1; l += 32) {
            int s0 = sm->seg[l], s1 = sm->seg[l + 1];
            if (s0 == s1) continue;
            u64 mx = 0;
            for (int j = s0 + lane; j < s1; j += 32) mx = umax64(mx, sm->keys[j]);
            u64 cur = wmax64(mx);
            float shift = __fmul_rn((float)(l + 1), off);
            int picks = 0;
            while (cur && picks < TOPN) {
                picks++;
                u32 pk = ~(u32)cur;
                float4 d4 = sm->sbox[pk >> 8];
                float px1 = __fadd_rn(d4.x, shift), py1 = __fadd_rn(d4.y, shift);
                float px2 = __fadd_rn(d4.z, shift), py2 = __fadd_rn(d4.w, shift);
                float pare = __fmul_rn(__fsub_rn(px2, px1), __fsub_rn(py2, py1));
                u64 nm = 0;
                for (int j = s0 + lane; j < s1; j += 32) {
                    u64 k = sm->keys[j];
                    if (k == 0ULL || (k & MARK)) continue;
                    if (k == cur) { sm->keys[j] = k | MARK; continue; }  /* keep pick */
                    u32 pk2 = ~(u32)k;
                    float4 c4 = sm->sbox[pk2 >> 8];
                    float x1 = __fadd_rn(c4.x, shift), y1 = __fadd_rn(c4.y, shift);
                    float x2 = __fadd_rn(c4.z, shift), y2 = __fadd_rn(c4.w, shift);
                    float ix1 = fmaxf(x1, px1), iy1 = fmaxf(y1, py1);
                    float ix2 = fminf(x2, px2), iy2 = fminf(y2, py2);
                    float inter = __fmul_rn(fmaxf(__fsub_rn(ix2, ix1), 0.f),
                                            fmaxf(__fsub_rn(iy2, iy1), 0.f));
                    float ar  = __fmul_rn(__fsub_rn(x2, x1), __fsub_rn(y2, y1));
                    float iou = __fdiv_rn(inter, __fsub_rn(__fadd_rn(ar, pare), inter));
                    if (iou > NMS_THRESH) sm->keys[j] = 0ULL;
                    else nm = umax64(nm, k);
                }
                cur = wmax64(nm);
            }
        }
        __syncthreads();

        /* ---- score histogram of survivors (marked picks) ---- */
        for (int j = tid; j < n; j += NTHR) {
            u64 k = sm->keys[j];
            if (k & MARK) {
                u32 khi = (u32)(k >> 32) & 0x7fffffffu;
                atomicAdd(&sm->hist[score_bin(khi)], 1);
                atomicAdd(&sm->misc[3], 1);
            }
        }
        __syncthreads();

        /* ---- threshold bin: smallest suffix with >= min(100,total) ---- */
        if (wid == 0) {
            int total = sm->misc[3];
            if (total == 0) {
                if (lane == 0) sm->misc[0] = 256;
            } else {
                int need = total < TOPN ? total : TOPN;
                int carry = 0; bool found = false;
                for (int r = 0; r < 8 && !found; r++) {
                    int bin = 255 - (r * 32 + lane);
                    int c = sm->hist[bin];
                    int v = c;
#pragma unroll
                    for (int d = 1; d < 32; d <<= 1) {
                        int t = __shfl_up_sync(0xffffffffu, v, d);
                        if (lane >= d) v += t;
                    }
                    int cum = carry + v;
                    unsigned ball = __ballot_sync(0xffffffffu, cum >= need);
                    if (ball) {
                        int ff = __ffs(ball) - 1;
                        if (lane == ff) sm->misc[0] = bin;
                        found = true;
                    }
                    carry += __shfl_sync(0xffffffffu, v, 31);
                }
                if (!found && lane == 0) sm->misc[0] = 0;
            }
        }
        __syncthreads();

        /* ---- compact survivors above threshold ---- */
        const int T = sm->misc[0];
        for (int j = tid; j < n; j += NTHR) {
            u64 k = sm->keys[j];
            if (k & MARK) {
                u64 kc = k & ~MARK;
                if (score_bin((u32)(kc >> 32)) >= T) {
                    int pos = atomicAdd(&sm->misc[2], 1);
                    if (pos < COMPCAP) sm->comp[pos] = kc;
                }
            }
        }
        __syncthreads();
        const int M = sm->misc[2];

        if (M <= COMPCAP) {
            /* exact rank by count (keys unique) -> write row = rank */
            for (int i = tid; i < M; i += NTHR) {
                u64 k = sm->comp[i];
                int r = 0;
                for (int j = 0; j < M; j++) r += (sm->comp[j] > k);
                if (r < TOPN) {
                    u32 pk = ~(u32)k;
                    int pr = (int)(pk >> 8), labf = (int)(pk & 255u);
                    float4 d4 = sm->sbox[pr];
                    float* orow = out + ((long)b * TOPN + r) * 6;
                    orow[0] = fminf(fmaxf(d4.x, 0.f), 1.f);
                    orow[1] = fminf(fmaxf(d4.y, 0.f), 1.f);
                    orow[2] = fminf(fmaxf(d4.z, 0.f), 1.f);
                    orow[3] = fminf(fmaxf(d4.w, 0.f), 1.f);
                    orow[4] = __uint_as_float((u32)(k >> 32));
                    orow[5] = (float)(labf + 1);
                }
            }
        } else {
            /* rare: iterative block argmax over marked survivors */
            for (int it = 0; it < TOPN; it++) {
                u64 bk = 0;
                for (int j = tid; j < n; j += NTHR) {
                    u64 k = sm->keys[j];
                    if (k & MARK) bk = umax64(bk, k & ~MARK);
                }
                bk = wmax64(bk);
                if (lane == 0) sm->red[wid] = bk;
                __syncthreads();
                if (tid == 0) {
                    for (int q = 1; q < 32; q++) bk = umax64(bk, sm->red[q]);
                    sm->red[0] = bk;
                }
                __syncthreads();
                bk = sm->red[0];
                if (bk == 0ULL) break;
                if (tid == 0) {
                    u32 pk = ~(u32)bk;
                    int pr = (int)(pk >> 8), labf = (int)(pk & 255u);
                    float4 d4 = sm->sbox[pr];
                    float* orow = out + ((long)b * TOPN + it) * 6;
                    orow[0] = fminf(fmaxf(d4.x, 0.f), 1.f);
                    orow[1] = fminf(fmaxf(d4.y, 0.f), 1.f);
                    orow[2] = fminf(fmaxf(d4.z, 0.f), 1.f);
                    orow[3] = fminf(fmaxf(d4.w, 0.f), 1.f);
                    orow[4] = __uint_as_float((u32)(bk >> 32));
                    orow[5] = (float)(labf + 1);
                }
                for (int j = tid; j < n; j += NTHR) {
                    u64 k = sm->keys[j];
                    if ((k & MARK) && (k & ~MARK) == bk) sm->keys[j] = 0ULL;
                }
                __syncthreads();
            }
        }
    } else {
        /* ---- exact fallback: flat rescan with per-candidate offsets ---- */
        u64* kp;
        if (n <= CAP) {
            const u64* gk = g_keys + (long)b * NCAND;
            for (int j = tid; j < n; j += NTHR) sm->keys[j] = gk[j];
            kp = sm->keys;
        } else {
            kp = g_keys + (long)b * NCAND;
        }
        __syncthreads();
        for (int it = 0; it < TOPN; it++) {
            u64 bk = 0;
            for (int j = tid; j < n; j += NTHR) bk = umax64(bk, kp[j]);
            bk = wmax64(bk);
            if (lane == 0) sm->red[wid] = bk;
            __syncthreads();
            if (tid == 0) {
                for (int k = 1; k < 32; k++) bk = umax64(bk, sm->red[k]);
                float* orow = out + ((long)b * TOPN + it) * 6;
                if (bk != 0ULL) {
                    u32 pk = ~(u32)bk;
                    int pr = (int)(pk >> 8), labf = (int)(pk & 255u);
                    float4 d4 = sm->sbox[pr];
                    float shift = __fmul_rn((float)(labf + 1), off);
                    float px1 = __fadd_rn(d4.x, shift), py1 = __fadd_rn(d4.y, shift);
                    float px2 = __fadd_rn(d4.z, shift), py2 = __fadd_rn(d4.w, shift);
                    sm->fbc[0] = px1; sm->fbc[1] = py1; sm->fbc[2] = px2; sm->fbc[3] = py2;
                    sm->fbc[4] = __fmul_rn(__fsub_rn(px2, px1), __fsub_rn(py2, py1));
                    sm->flag = 1;
                    orow[0] = fminf(fmaxf(d4.x, 0.f), 1.f);
                    orow[1] = fminf(fmaxf(d4.y, 0.f), 1.f);
                    orow[2] = fminf(fmaxf(d4.z, 0.f), 1.f);
                    orow[3] = fminf(fmaxf(d4.w, 0.f), 1.f);
                    orow[4] = __uint_as_float((u32)(bk >> 32));
                    orow[5] = (float)(labf + 1);
                } else {
                    sm->flag = 0;
                }
            }
            __syncthreads();
            if (sm->flag) {
                float px1 = sm->fbc[0], py1 = sm->fbc[1];
                float px2 = sm->fbc[2], py2 = sm->fbc[3], pare = sm->fbc[4];
                for (int j = tid; j < n; j += NTHR) {
                    u64 k = kp[j];
                    if (!k) continue;
                    u32 pk2 = ~(u32)k;
                    float4 c4 = sm->sbox[pk2 >> 8];
                    float shift2 = __fmul_rn((float)((pk2 & 255u) + 1), off);
                    float x1 = __fadd_rn(c4.x, shift2), y1 = __fadd_rn(c4.y, shift2);
                    float x2 = __fadd_rn(c4.z, shift2), y2 = __fadd_rn(c4.w, shift2);
                    float ix1 = fmaxf(x1, px1), iy1 = fmaxf(y1, py1);
                    float ix2 = fminf(x2, px2), iy2 = fminf(y2, py2);
                    float inter = __fmul_rn(fmaxf(__fsub_rn(ix2, ix1), 0.f),
                                            fmaxf(__fsub_rn(iy2, iy1), 0.f));
                    float ar  = __fmul_rn(__fsub_rn(x2, x1), __fsub_rn(y2, y1));
                    float iou = __fdiv_rn(inter, __fsub_rn(__fadd_rn(ar, pare), inter));
                    if (iou > NMS_THRESH) kp[j] = 0ULL;
                }
            }
            __syncthreads();
        }
    }

    /* restore zero state for next graph replay */
    if (tid == 0) { g_count[b] = 0; g_maxbits[b] = 0u; g_minbits[b] = 0u; }
}

extern "C" void kernel_launch(void* const* d_in, const int* in_sizes, int n_in,
                              void* d_out, int out_size) {
    const float *deltas = nullptr, *obj = nullptr, *priors = nullptr;
    for (int i = 0; i < n_in; i++) {
        if      (in_sizes[i] == BATCH * NPRI * 4)    deltas = (const float*)d_in[i];
        else if (in_sizes[i] == BATCH * NPRI * NCLS) obj    = (const float*)d_in[i];
        else if (in_sizes[i] == NPRI * 4)            priors = (const float*)d_in[i];
    }
    cudaFuncSetAttribute(nms_kernel, cudaFuncAttributeMaxDynamicSharedMemorySize,
                         (int)sizeof(Sm));
    dim3 g(NPRI / 8, BATCH);
    stage_a<<<g, 256>>>(deltas, obj, priors);
    nms_kernel<<<BATCH, NTHR, sizeof(Sm)>>>((float*)d_out);
}

// round 8
// speedup vs baseline: 13.2795x; 13.2795x over previous
#include <cuda_runtime.h>

typedef unsigned long long u64;
typedef unsigned int u32;

#define BATCH 16
#define NPRI  3000
#define NCLS  201
#define CM1   200
#define NCAND (NPRI * CM1)
#define TOPN  100
#define SCORE_THRESH 0.02f
#define NMS_THRESH   0.45f
#define WCAP  6144
#define NTHR  1024

/* ---- static device scratch (zero-init at load; nms restores zeros) ---- */
__device__ u64    g_keys[(long)BATCH * NCAND];
__device__ int    g_count[BATCH];
__device__ u32    g_maxbits[BATCH];   /* max fenc(coord)          */
__device__ u32    g_minbits[BATCH];   /* max fenc(-coord) => min  */
__device__ float4 g_decoded[BATCH * NPRI];

__device__ __forceinline__ u64 umax64(u64 a, u64 b) { return a > b ? a : b; }

__device__ __forceinline__ unsigned fenc(float f) {
    unsigned u = __float_as_uint(f);
    return (u & 0x80000000u) ? ~u : (u | 0x80000000u);
}
__device__ __forceinline__ float fdec(unsigned e) {
    unsigned u = (e & 0x80000000u) ? (e & 0x7fffffffu) : ~e;
    return __uint_as_float(u);
}

/* warp max of u64 via 2x 32-bit REDUX (low word = ~flat_idx => tie->smallest idx) */
__device__ __forceinline__ u64 wmax64(u64 k) {
    u32 hi = (u32)(k >> 32);
    u32 mh = __reduce_max_sync(0xffffffffu, hi);
    u32 ml = __reduce_max_sync(0xffffffffu, (hi == mh) ? (u32)k : 0u);
    return ((u64)mh << 32) | ml;
}

/* score (positive float bits) -> 256-bin monotone bucket over (0.02, 1.0] */
__device__ __forceinline__ int score_bin(u32 khi) {
    int v = (int)(khi >> 18) - 3880;     /* 0x3CA3D70A>>18 = 3880 */
    return v < 0 ? 0 : (v > 255 ? 255 : v);
}

/* grid (NPRI/8, BATCH), block 256: one warp per (image, prior) row */
__global__ void stage_a(const float* __restrict__ deltas,
                        const float* __restrict__ obj,
                        const float* __restrict__ priors) {
    const int lane = threadIdx.x & 31;
    const int wid  = threadIdx.x >> 5;
    const int p    = blockIdx.x * 8 + wid;
    const int b    = blockIdx.y;
    const long row = (long)b * NPRI + p;
    const float* o = obj + row * NCLS;

    __shared__ int s_cnt, s_off;
    if (threadIdx.x == 0) s_cnt = 0;
    __syncthreads();

    /* softmax over 201 classes */
    float v[7];
    float m = -3.4e38f;
#pragma unroll
    for (int k = 0; k < 7; k++) {
        int c = lane + 32 * k;
        v[k] = (c < NCLS) ? o[c] : -3.4e38f;
        m = fmaxf(m, v[k]);
    }
#pragma unroll
    for (int d = 16; d; d >>= 1) m = fmaxf(m, __shfl_xor_sync(0xffffffffu, m, d));
    float e[7]; float sum = 0.f;
#pragma unroll
    for (int k = 0; k < 7; k++) {
        int c = lane + 32 * k;
        e[k] = (c < NCLS) ? expf(v[k] - m) : 0.f;
        sum += e[k];
    }
#pragma unroll
    for (int d = 16; d; d >>= 1) sum += __shfl_xor_sync(0xffffffffu, sum, d);

    /* prefilter (no false negatives), exact divide only for ~3% of elems */
    const float pre = 0.0195f * sum;
    float prob[7]; int pass[7]; int cnt = 0;
#pragma unroll
    for (int k = 0; k < 7; k++) {
        int c = lane + 32 * k;
        pass[k] = 0;
        if (c >= 1 && c < NCLS && e[k] > pre) {
            float pv = __fdiv_rn(e[k], sum);
            if (pv > SCORE_THRESH) { pass[k] = 1; prob[k] = pv; }
        }
        cnt += pass[k];
    }
    int inc = cnt;
#pragma unroll
    for (int d = 1; d < 32; d <<= 1) {
        int t = __shfl_up_sync(0xffffffffu, inc, d);
        if (lane >= d) inc += t;
    }
    int total = __shfl_sync(0xffffffffu, inc, 31);
    int excl  = inc - cnt;

    int wbase = 0;
    if (lane == 0 && total > 0) wbase = atomicAdd(&s_cnt, total);
    wbase = __shfl_sync(0xffffffffu, wbase, 0);
    __syncthreads();
    if (threadIdx.x == 0) s_off = s_cnt ? atomicAdd(&g_count[b], s_cnt) : 0;
    __syncthreads();

    u64* kd = g_keys + (long)b * NCAND;
    int w = s_off + wbase + excl;
#pragma unroll
    for (int k = 0; k < 7; k++) {
        if (pass[k]) {
            int c = lane + 32 * k;
            u32 pk = ((u32)p << 8) | (u32)(c - 1);
            kd[w] = ((u64)__float_as_uint(prob[k]) << 32) | (u32)(~pk);
            w++;
        }
    }

    if (lane == 0) {
        float4 dl = ((const float4*)deltas)[row];
        float4 pr = ((const float4*)priors)[p];
        float pw = pr.z, ph = pr.w;
        float cx = dl.x * 0.1f * pw + pr.x;
        float cy = dl.y * 0.1f * ph + pr.y;
        float bw = expf(dl.z * 0.2f) * pw;
        float bh = expf(dl.w * 0.2f) * ph;
        float x1 = cx - 0.5f * bw, y1 = cy - 0.5f * bh;
        float x2 = cx + 0.5f * bw, y2 = cy + 0.5f * bh;
        g_decoded[row] = make_float4(x1, y1, x2, y2);
        float mm = fmaxf(fmaxf(x1, y1), fmaxf(x2, y2));
        float mn = fminf(fminf(x1, y1), fminf(x2, y2));
        atomicMax(&g_maxbits[b], fenc(mm));
        atomicMax(&g_minbits[b], fenc(-mn));
    }
}

struct Sm {
    float4 sbox[NPRI];        /* 48 KB decoded boxes */
    u64    keysc[WCAP];       /* thresholded, label-grouped candidates */
    u64    comp[WCAP];        /* emitted picks (superset of top-100)   */
    u64    lmax[CM1];         /* per-label max key */
    u64    red[32];
    int    hist[256];
    int    seg[CM1 + 1];
    int    cnt[CM1];
    int    cur[CM1];
    int    misc[8];           /* 0:B 1:nlab 2:M 3:included 4:flag */
    float  fbc[8];
};

__global__ void __launch_bounds__(NTHR) nms_kernel(float* __restrict__ out) {
    extern __shared__ char smraw[];
    Sm* sm = (Sm*)smraw;
    const int b   = blockIdx.x;
    const int tid = threadIdx.x;
    const int wid = tid >> 5, lane = tid & 31;

    const int   n    = g_count[b];
    const float off  = fdec(g_maxbits[b]) + 1.0f;
    const float minv = -fdec(g_minbits[b]);
    const bool  fast = (minv > -1.0f);

    /* pre-zero output rows for this image */
    for (int q = tid; q < TOPN * 6; q += NTHR) out[(long)b * TOPN * 6 + q] = 0.f;

    for (int i = tid; i < NPRI; i += NTHR)
        sm->sbox[i] = g_decoded[b * NPRI + i];

    bool seq = !fast;
    const u64* gk = g_keys + (long)b * NCAND;

    if (fast) {
        for (int l = tid; l < CM1; l += NTHR) { sm->lmax[l] = 0; sm->cnt[l] = 0; sm->cur[l] = 0; }
        if (tid < 256) sm->hist[tid] = 0;
        if (tid < 8)   sm->misc[tid] = 0;
        __syncthreads();

        /* pass 1: per-label max key */
        for (int j = tid; j < n; j += NTHR) {
            u64 k = gk[j];
            atomicMax(&sm->lmax[(~(u32)k) & 255u], k);
        }
        __syncthreads();

        /* histogram of label maxes */
        if (tid < CM1 && sm->lmax[tid]) {
            atomicAdd(&sm->hist[score_bin((u32)(sm->lmax[tid] >> 32))], 1);
            atomicAdd(&sm->misc[1], 1);
        }
        __syncthreads();

        /* threshold bin B: smallest suffix of label-max bins with count >= TOPN.
           (>=100 label-maxes in bins >= B are all guaranteed global picks ->
            the 100th global pick >= bin-B floor -> bins < B are irrelevant.) */
        if (wid == 0) {
            int nlab = sm->misc[1];
            if (nlab < TOPN) {
                if (lane == 0) sm->misc[0] = 0;
            } else {
                int carry = 0; bool found = false;
                for (int r = 0; r < 8 && !found; r++) {
                    int bin = 255 - (r * 32 + lane);
                    int c = sm->hist[bin];
                    int v = c;
#pragma unroll
                    for (int d = 1; d < 32; d <<= 1) {
                        int t = __shfl_up_sync(0xffffffffu, v, d);
                        if (lane >= d) v += t;
                    }
                    int cum = carry + v;
                    unsigned ball = __ballot_sync(0xffffffffu, cum >= TOPN);
                    if (ball) {
                        int ff = __ffs(ball) - 1;
                        if (lane == ff) sm->misc[0] = bin;
                        found = true;
                    }
                    carry += __shfl_sync(0xffffffffu, v, 31);
                }
                if (!found && lane == 0) sm->misc[0] = 0;
            }
        }
        __syncthreads();
        const int B = sm->misc[0];

        /* pass 2: count candidates with bin >= B per label */
        for (int j = tid; j < n; j += NTHR) {
            u64 k = gk[j];
            if (score_bin((u32)(k >> 32)) >= B) {
                atomicAdd(&sm->cnt[(~(u32)k) & 255u], 1);
                atomicAdd(&sm->misc[3], 1);
            }
        }
        __syncthreads();

        if (sm->misc[3] > WCAP) {
            seq = true;                       /* overflow -> exact fallback */
        } else {
            /* prefix sum -> segments */
            if (wid == 0) {
                int carry = 0;
#pragma unroll
                for (int c = 0; c < 7; c++) {
                    int l = c * 32 + lane;
                    int h = (l < CM1) ? sm->cnt[l] : 0;
                    int v = h;
#pragma unroll
                    for (int d = 1; d < 32; d <<= 1) {
                        int t = __shfl_up_sync(0xffffffffu, v, d);
                        if (lane >= d) v += t;
                    }
                    if (l < CM1) sm->seg[l] = carry + v - h;
                    carry += __shfl_sync(0xffffffffu, v, 31);
                }
                if (lane == 0) sm->seg[CM1] = carry;
            }
            __syncthreads();

            /* pass 3: scatter thresholded candidates by label */
            for (int j = tid; j < n; j += NTHR) {
                u64 k = gk[j];
                if (score_bin((u32)(k >> 32)) >= B) {
                    int labf = (int)((~(u32)k) & 255u);
                    int pos  = sm->seg[labf] + atomicAdd(&sm->cur[labf], 1);
                    sm->keysc[pos] = k;
                }
            }
            __syncthreads();

            /* parallel per-label greedy NMS on tiny segments, one label/warp */
            for (int l = wid; l < CM1; l += 32) {
                int s0 = sm->seg[l], s1 = sm->seg[l + 1];
                if (s0 == s1) continue;
                u64 mx = 0;
                for (int j = s0 + lane; j < s1; j += 32) mx = umax64(mx, sm->keysc[j]);
                u64 cur = wmax64(mx);
                float shift = __fmul_rn((float)(l + 1), off);
                int picks = 0;
                while (cur && picks < TOPN) {
                    picks++;
                    if (lane == 0) {
                        int pos = atomicAdd(&sm->misc[2], 1);
                        sm->comp[pos] = cur;
                    }
                    u32 pk = ~(u32)cur;
                    float4 d4 = sm->sbox[pk >> 8];
                    float px1 = __fadd_rn(d4.x, shift), py1 = __fadd_rn(d4.y, shift);
                    float px2 = __fadd_rn(d4.z, shift), py2 = __fadd_rn(d4.w, shift);
                    float pare = __fmul_rn(__fsub_rn(px2, px1), __fsub_rn(py2, py1));
                    u64 nm = 0;
                    for (int j = s0 + lane; j < s1; j += 32) {
                        u64 k = sm->keysc[j];
                        if (k == 0ULL) continue;
                        if (k == cur) { sm->keysc[j] = 0ULL; continue; }
                        u32 pk2 = ~(u32)k;
                        float4 c4 = sm->sbox[pk2 >> 8];
                        float x1 = __fadd_rn(c4.x, shift), y1 = __fadd_rn(c4.y, shift);
                        float x2 = __fadd_rn(c4.z, shift), y2 = __fadd_rn(c4.w, shift);
                        float ix1 = fmaxf(x1, px1), iy1 = fmaxf(y1, py1);
                        float ix2 = fminf(x2, px2), iy2 = fminf(y2, py2);
                        float inter = __fmul_rn(fmaxf(__fsub_rn(ix2, ix1), 0.f),
                                                fmaxf(__fsub_rn(iy2, iy1), 0.f));
                        float ar  = __fmul_rn(__fsub_rn(x2, x1), __fsub_rn(y2, y1));
                        float iou = __fdiv_rn(inter, __fsub_rn(__fadd_rn(ar, pare), inter));
                        if (iou > NMS_THRESH) sm->keysc[j] = 0ULL;
                        else nm = umax64(nm, k);
                    }
                    cur = wmax64(nm);
                }
            }
            __syncthreads();

            /* exact rank-by-count over emitted picks (global order = key desc) */
            const int M = sm->misc[2];
            for (int i = tid; i < M; i += NTHR) {
                u64 k = sm->comp[i];
                int r = 0;
                for (int j = 0; j < M; j++) r += (sm->comp[j] > k);
                if (r < TOPN) {
                    u32 pk = ~(u32)k;
                    int pr = (int)(pk >> 8), labf = (int)(pk & 255u);
                    float4 d4 = sm->sbox[pr];
                    float* orow = out + ((long)b * TOPN + r) * 6;
                    orow[0] = fminf(fmaxf(d4.x, 0.f), 1.f);
                    orow[1] = fminf(fmaxf(d4.y, 0.f), 1.f);
                    orow[2] = fminf(fmaxf(d4.z, 0.f), 1.f);
                    orow[3] = fminf(fmaxf(d4.w, 0.f), 1.f);
                    orow[4] = __uint_as_float((u32)(k >> 32));
                    orow[5] = (float)(labf + 1);
                }
            }
        }
    }

    if (seq) {
        /* exact sequential fallback: global 100-pick loop over g_keys (L2).
           Mutates g_keys; safe — stage_a rebuilds them every replay. */
        u64* kp = g_keys + (long)b * NCAND;
        __syncthreads();
        for (int it = 0; it < TOPN; it++) {
            u64 bk = 0;
            for (int j = tid; j < n; j += NTHR) bk = umax64(bk, kp[j]);
            bk = wmax64(bk);
            if (lane == 0) sm->red[wid] = bk;
            __syncthreads();
            if (tid == 0) {
                for (int k = 1; k < 32; k++) bk = umax64(bk, sm->red[k]);
                sm->red[0] = bk;
                if (bk != 0ULL) {
                    u32 pk = ~(u32)bk;
                    int pr = (int)(pk >> 8), labf = (int)(pk & 255u);
                    float4 d4 = sm->sbox[pr];
                    float shift = __fmul_rn((float)(labf + 1), off);
                    float px1 = __fadd_rn(d4.x, shift), py1 = __fadd_rn(d4.y, shift);
                    float px2 = __fadd_rn(d4.z, shift), py2 = __fadd_rn(d4.w, shift);
                    sm->fbc[0] = px1; sm->fbc[1] = py1; sm->fbc[2] = px2; sm->fbc[3] = py2;
                    sm->fbc[4] = __fmul_rn(__fsub_rn(px2, px1), __fsub_rn(py2, py1));
                    float* orow = out + ((long)b * TOPN + it) * 6;
                    orow[0] = fminf(fmaxf(d4.x, 0.f), 1.f);
                    orow[1] = fminf(fmaxf(d4.y, 0.f), 1.f);
                    orow[2] = fminf(fmaxf(d4.z, 0.f), 1.f);
                    orow[3] = fminf(fmaxf(d4.w, 0.f), 1.f);
                    orow[4] = __uint_as_float((u32)(bk >> 32));
                    orow[5] = (float)(labf + 1);
                }
            }
            __syncthreads();
            u64 pick = sm->red[0];
            if (pick == 0ULL) break;
            float px1 = sm->fbc[0], py1 = sm->fbc[1];
            float px2 = sm->fbc[2], py2 = sm->fbc[3], pare = sm->fbc[4];
            for (int j = tid; j < n; j += NTHR) {
                u64 k = kp[j];
                if (!k) continue;
                if (k == pick) { kp[j] = 0ULL; continue; }
                u32 pk2 = ~(u32)k;
                float4 c4 = sm->sbox[pk2 >> 8];
                float shift2 = __fmul_rn((float)((pk2 & 255u) + 1), off);
                float x1 = __fadd_rn(c4.x, shift2), y1 = __fadd_rn(c4.y, shift2);
                float x2 = __fadd_rn(c4.z, shift2), y2 = __fadd_rn(c4.w, shift2);
                float ix1 = fmaxf(x1, px1), iy1 = fmaxf(y1, py1);
                float ix2 = fminf(x2, px2), iy2 = fminf(y2, py2);
                float inter = __fmul_rn(fmaxf(__fsub_rn(ix2, ix1), 0.f),
                                        fmaxf(__fsub_rn(iy2, iy1), 0.f));
                float ar  = __fmul_rn(__fsub_rn(x2, x1), __fsub_rn(y2, y1));
                float iou = __fdiv_rn(inter, __fsub_rn(__fadd_rn(ar, pare), inter));
                if (iou > NMS_THRESH) kp[j] = 0ULL;
            }
            __syncthreads();
        }
    }

    /* restore zero state for next graph replay */
    if (tid == 0) { g_count[b] = 0; g_maxbits[b] = 0u; g_minbits[b] = 0u; }
}

extern "C" void kernel_launch(void* const* d_in, const int* in_sizes, int n_in,
                              void* d_out, int out_size) {
    const float *deltas = nullptr, *obj = nullptr, *priors = nullptr;
    for (int i = 0; i < n_in; i++) {
        if      (in_sizes[i] == BATCH * NPRI * 4)    deltas = (const float*)d_in[i];
        else if (in_sizes[i] == BATCH * NPRI * NCLS) obj    = (const float*)d_in[i];
        else if (in_sizes[i] == NPRI * 4)            priors = (const float*)d_in[i];
    }
    cudaFuncSetAttribute(nms_kernel, cudaFuncAttributeMaxDynamicSharedMemorySize,
                         (int)sizeof(Sm));
    dim3 g(NPRI / 8, BATCH);
    stage_a<<<g, 256>>>(deltas, obj, priors);
    nms_kernel<<<BATCH, NTHR, sizeof(Sm)>>>((float*)d_out);
}

// round 9
// speedup vs baseline: 15.2123x; 1.1455x over previous
#include <cuda_runtime.h>

typedef unsigned long long u64;
typedef unsigned int u32;

#define BATCH 16
#define NPRI  3000
#define NCLS  201
#define CM1   200
#define NCAND (NPRI * CM1)
#define TOPN  100
#define SCORE_THRESH 0.02f
#define NMS_THRESH   0.45f
#define NTHR  1024
#define BKT   64            /* per-label bucket capacity  */
#define CCAP  4096          /* emitted-pick capacity      */

/* ---- static device scratch (zero-init at load; nms restores zeros) ---- */
__device__ u64    g_keys[(long)BATCH * NCAND];
__device__ u64    g_lmax[BATCH * 256];      /* per-(image,label) max key */
__device__ int    g_count[BATCH];
__device__ u32    g_maxbits[BATCH];         /* max fenc(coord)          */
__device__ u32    g_minbits[BATCH];         /* max fenc(-coord) => min  */
__device__ float4 g_decoded[BATCH * NPRI];

__device__ __forceinline__ u64 umax64(u64 a, u64 b) { return a > b ? a : b; }

__device__ __forceinline__ unsigned fenc(float f) {
    unsigned u = __float_as_uint(f);
    return (u & 0x80000000u) ? ~u : (u | 0x80000000u);
}
__device__ __forceinline__ float fdec(unsigned e) {
    unsigned u = (e & 0x80000000u) ? (e & 0x7fffffffu) : ~e;
    return __uint_as_float(u);
}

/* warp max of u64 via 2x 32-bit REDUX (low word = ~flat_idx => tie->smallest idx) */
__device__ __forceinline__ u64 wmax64(u64 k) {
    u32 hi = (u32)(k >> 32);
    u32 mh = __reduce_max_sync(0xffffffffu, hi);
    u32 ml = __reduce_max_sync(0xffffffffu, (hi == mh) ? (u32)k : 0u);
    return ((u64)mh << 32) | ml;
}

/* score (positive float bits) -> 256-bin monotone bucket over (0.02, 1.0] */
__device__ __forceinline__ int score_bin(u32 khi) {
    int v = (int)(khi >> 18) - 3880;     /* 0x3CA3D70A>>18 = 3880 */
    return v < 0 ? 0 : (v > 255 ? 255 : v);
}

/* grid (NPRI/8, BATCH), block 256: one warp per (image, prior) row */
__global__ void stage_a(const float* __restrict__ deltas,
                        const float* __restrict__ obj,
                        const float* __restrict__ priors) {
    const int lane = threadIdx.x & 31;
    const int wid  = threadIdx.x >> 5;
    const int p    = blockIdx.x * 8 + wid;
    const int b    = blockIdx.y;
    const long row = (long)b * NPRI + p;
    const float* o = obj + row * NCLS;

    __shared__ int s_cnt, s_off;
    if (threadIdx.x == 0) s_cnt = 0;
    __syncthreads();

    /* softmax over 201 classes */
    float v[7];
    float m = -3.4e38f;
#pragma unroll
    for (int k = 0; k < 7; k++) {
        int c = lane + 32 * k;
        v[k] = (c < NCLS) ? o[c] : -3.4e38f;
        m = fmaxf(m, v[k]);
    }
#pragma unroll
    for (int d = 16; d; d >>= 1) m = fmaxf(m, __shfl_xor_sync(0xffffffffu, m, d));
    float e[7]; float sum = 0.f;
#pragma unroll
    for (int k = 0; k < 7; k++) {
        int c = lane + 32 * k;
        e[k] = (c < NCLS) ? expf(v[k] - m) : 0.f;
        sum += e[k];
    }
#pragma unroll
    for (int d = 16; d; d >>= 1) sum += __shfl_xor_sync(0xffffffffu, sum, d);

    /* prefilter (no false negatives), exact divide only for ~3% of elems */
    const float pre = 0.0195f * sum;
    float prob[7]; int pass[7]; int cnt = 0;
#pragma unroll
    for (int k = 0; k < 7; k++) {
        int c = lane + 32 * k;
        pass[k] = 0;
        if (c >= 1 && c < NCLS && e[k] > pre) {
            float pv = __fdiv_rn(e[k], sum);
            if (pv > SCORE_THRESH) { pass[k] = 1; prob[k] = pv; }
        }
        cnt += pass[k];
    }
    int inc = cnt;
#pragma unroll
    for (int d = 1; d < 32; d <<= 1) {
        int t = __shfl_up_sync(0xffffffffu, inc, d);
        if (lane >= d) inc += t;
    }
    int total = __shfl_sync(0xffffffffu, inc, 31);
    int excl  = inc - cnt;

    int wbase = 0;
    if (lane == 0 && total > 0) wbase = atomicAdd(&s_cnt, total);
    wbase = __shfl_sync(0xffffffffu, wbase, 0);
    __syncthreads();
    if (threadIdx.x == 0) s_off = s_cnt ? atomicAdd(&g_count[b], s_cnt) : 0;
    __syncthreads();

    u64* kd = g_keys + (long)b * NCAND;
    int w = s_off + wbase + excl;
#pragma unroll
    for (int k = 0; k < 7; k++) {
        if (pass[k]) {
            int c = lane + 32 * k;
            u32 pk = ((u32)p << 8) | (u32)(c - 1);
            u64 key = ((u64)__float_as_uint(prob[k]) << 32) | (u32)(~pk);
            kd[w] = key;
            atomicMax(&g_lmax[b * 256 + (c - 1)], key);   /* per-label max */
            w++;
        }
    }

    if (lane == 0) {
        float4 dl = ((const float4*)deltas)[row];
        float4 pr = ((const float4*)priors)[p];
        float pw = pr.z, ph = pr.w;
        float cx = dl.x * 0.1f * pw + pr.x;
        float cy = dl.y * 0.1f * ph + pr.y;
        float bw = expf(dl.z * 0.2f) * pw;
        float bh = expf(dl.w * 0.2f) * ph;
        float x1 = cx - 0.5f * bw, y1 = cy - 0.5f * bh;
        float x2 = cx + 0.5f * bw, y2 = cy + 0.5f * bh;
        g_decoded[row] = make_float4(x1, y1, x2, y2);
        float mm = fmaxf(fmaxf(x1, y1), fmaxf(x2, y2));
        float mn = fminf(fminf(x1, y1), fminf(x2, y2));
        atomicMax(&g_maxbits[b], fenc(mm));
        atomicMax(&g_minbits[b], fenc(-mn));
    }
}

struct Sm {
    u64 bucket[CM1 * BKT];    /* 100 KB per-label thresholded candidates */
    u64 comp[CCAP];           /* emitted picks */
    u64 red[32];
    int bcnt[CM1];
    int hist[256];
    int misc[8];              /* 0:B 1:nlab 2:M 3:overflow */
    float fbc[8];
};

__global__ void __launch_bounds__(NTHR) nms_kernel(float* __restrict__ out) {
    extern __shared__ char smraw[];
    Sm* sm = (Sm*)smraw;
    const int b   = blockIdx.x;
    const int tid = threadIdx.x;
    const int wid = tid >> 5, lane = tid & 31;

    const int   n    = g_count[b];
    const float off  = fdec(g_maxbits[b]) + 1.0f;
    const float minv = -fdec(g_minbits[b]);
    const bool  fast = (minv > -1.0f);
    const u64*  gk   = g_keys + (long)b * NCAND;
    const float4* dec = g_decoded + (long)b * NPRI;

    for (int q = tid; q < TOPN * 6; q += NTHR) out[(long)b * TOPN * 6 + q] = 0.f;

    bool seq = !fast;

    if (fast) {
        for (int l = tid; l < CM1; l += NTHR) sm->bcnt[l] = 0;
        if (tid < 256) sm->hist[tid] = 0;
        if (tid < 8)   sm->misc[tid] = 0;
        __syncthreads();

        /* histogram of per-label maxes (computed by stage_a) */
        if (tid < CM1) {
            u64 lm = g_lmax[b * 256 + tid];
            if (lm) {
                atomicAdd(&sm->hist[score_bin((u32)(lm >> 32))], 1);
                atomicAdd(&sm->misc[1], 1);
            }
        }
        __syncthreads();

        /* threshold bin B: smallest suffix of label-max bins with count >= TOPN */
        if (wid == 0) {
            int nlab = sm->misc[1];
            if (nlab < TOPN) {
                if (lane == 0) sm->misc[0] = 0;
            } else {
                int carry = 0; bool found = false;
                for (int r = 0; r < 8 && !found; r++) {
                    int bin = 255 - (r * 32 + lane);
                    int c = sm->hist[bin];
                    int v = c;
#pragma unroll
                    for (int d = 1; d < 32; d <<= 1) {
                        int t = __shfl_up_sync(0xffffffffu, v, d);
                        if (lane >= d) v += t;
                    }
                    int cum = carry + v;
                    unsigned ball = __ballot_sync(0xffffffffu, cum >= TOPN);
                    if (ball) {
                        int ff = __ffs(ball) - 1;
                        if (lane == ff) sm->misc[0] = bin;
                        found = true;
                    }
                    carry += __shfl_sync(0xffffffffu, v, 31);
                }
                if (!found && lane == 0) sm->misc[0] = 0;
            }
        }
        __syncthreads();
        const int B = sm->misc[0];

        /* single filtered pass: append bin>=B candidates into label buckets */
        for (int j = tid; j < n; j += NTHR) {
            u64 k = gk[j];
            if (score_bin((u32)(k >> 32)) >= B) {
                int labf = (int)((~(u32)k) & 255u);
                int pos = atomicAdd(&sm->bcnt[labf], 1);
                if (pos < BKT) sm->bucket[labf * BKT + pos] = k;
                else sm->misc[3] = 1;
            }
        }
        __syncthreads();

        if (sm->misc[3]) {
            seq = true;
        } else {
            /* per-label greedy NMS: one label per warp, segment in registers */
            for (int l = wid; l < CM1; l += 32) {
                int c = sm->bcnt[l];
                if (c == 0) continue;
                u64 a0 = (lane < c)      ? sm->bucket[l * BKT + lane]      : 0ULL;
                u64 a1 = (lane + 32 < c) ? sm->bucket[l * BKT + lane + 32] : 0ULL;
                float4 b0 = make_float4(0.f,0.f,0.f,0.f), b1 = b0;
                if (a0) b0 = dec[(int)((~(u32)a0) >> 8)];
                if (a1) b1 = dec[(int)((~(u32)a1) >> 8)];
                float shift = __fmul_rn((float)(l + 1), off);
                u64 cur = wmax64(umax64(a0, a1));
                while (cur) {
                    if (lane == 0) {
                        int pos = atomicAdd(&sm->misc[2], 1);
                        if (pos < CCAP) sm->comp[pos] = cur;
                    }
                    float4 d4 = dec[(int)((~(u32)cur) >> 8)];   /* broadcast load */
                    float px1 = __fadd_rn(d4.x, shift), py1 = __fadd_rn(d4.y, shift);
                    float px2 = __fadd_rn(d4.z, shift), py2 = __fadd_rn(d4.w, shift);
                    float pare = __fmul_rn(__fsub_rn(px2, px1), __fsub_rn(py2, py1));
#pragma unroll
                    for (int s = 0; s < 2; s++) {
                        u64 k = s ? a1 : a0;
                        if (!k) continue;
                        if (k == cur) { if (s) a1 = 0; else a0 = 0; continue; }
                        float4 c4 = s ? b1 : b0;
                        float x1 = __fadd_rn(c4.x, shift), y1 = __fadd_rn(c4.y, shift);
                        float x2 = __fadd_rn(c4.z, shift), y2 = __fadd_rn(c4.w, shift);
                        float ix1 = fmaxf(x1, px1), iy1 = fmaxf(y1, py1);
                        float ix2 = fminf(x2, px2), iy2 = fminf(y2, py2);
                        float inter = __fmul_rn(fmaxf(__fsub_rn(ix2, ix1), 0.f),
                                                fmaxf(__fsub_rn(iy2, iy1), 0.f));
                        float ar  = __fmul_rn(__fsub_rn(x2, x1), __fsub_rn(y2, y1));
                        float iou = __fdiv_rn(inter, __fsub_rn(__fadd_rn(ar, pare), inter));
                        if (iou > NMS_THRESH) { if (s) a1 = 0; else a0 = 0; }
                    }
                    cur = wmax64(umax64(a0, a1));
                }
            }
            __syncthreads();

            const int M = sm->misc[2];
            if (M > CCAP) {
                seq = true;
            } else {
                /* exact rank-by-count (keys unique): row = #keys greater */
                for (int i = tid; i < M; i += NTHR) {
                    u64 k = sm->comp[i];
                    int r = 0;
                    for (int j = 0; j < M; j++) r += (sm->comp[j] > k);
                    if (r < TOPN) {
                        u32 pk = ~(u32)k;
                        int pr = (int)(pk >> 8), labf = (int)(pk & 255u);
                        float4 d4 = dec[pr];
                        float* orow = out + ((long)b * TOPN + r) * 6;
                        orow[0] = fminf(fmaxf(d4.x, 0.f), 1.f);
                        orow[1] = fminf(fmaxf(d4.y, 0.f), 1.f);
                        orow[2] = fminf(fmaxf(d4.z, 0.f), 1.f);
                        orow[3] = fminf(fmaxf(d4.w, 0.f), 1.f);
                        orow[4] = __uint_as_float((u32)(k >> 32));
                        orow[5] = (float)(labf + 1);
                    }
                }
            }
        }
    }

    if (seq) {
        /* exact sequential fallback over g_keys (boxes from L2) */
        u64* kp = g_keys + (long)b * NCAND;
        __syncthreads();
        for (int it = 0; it < TOPN; it++) {
            u64 bk = 0;
            for (int j = tid; j < n; j += NTHR) bk = umax64(bk, kp[j]);
            bk = wmax64(bk);
            if (lane == 0) sm->red[wid] = bk;
            __syncthreads();
            if (tid == 0) {
                for (int k = 1; k < 32; k++) bk = umax64(bk, sm->red[k]);
                sm->red[0] = bk;
                if (bk != 0ULL) {
                    u32 pk = ~(u32)bk;
                    int pr = (int)(pk >> 8), labf = (int)(pk & 255u);
                    float4 d4 = dec[pr];
                    float shift = __fmul_rn((float)(labf + 1), off);
                    float px1 = __fadd_rn(d4.x, shift), py1 = __fadd_rn(d4.y, shift);
                    float px2 = __fadd_rn(d4.z, shift), py2 = __fadd_rn(d4.w, shift);
                    sm->fbc[0] = px1; sm->fbc[1] = py1; sm->fbc[2] = px2; sm->fbc[3] = py2;
                    sm->fbc[4] = __fmul_rn(__fsub_rn(px2, px1), __fsub_rn(py2, py1));
                    float* orow = out + ((long)b * TOPN + it) * 6;
                    orow[0] = fminf(fmaxf(d4.x, 0.f), 1.f);
                    orow[1] = fminf(fmaxf(d4.y, 0.f), 1.f);
                    orow[2] = fminf(fmaxf(d4.z, 0.f), 1.f);
                    orow[3] = fminf(fmaxf(d4.w, 0.f), 1.f);
                    orow[4] = __uint_as_float((u32)(bk >> 32));
                    orow[5] = (float)(labf + 1);
                }
            }
            __syncthreads();
            u64 pick = sm->red[0];
            if (pick == 0ULL) break;
            float px1 = sm->fbc[0], py1 = sm->fbc[1];
            float px2 = sm->fbc[2], py2 = sm->fbc[3], pare = sm->fbc[4];
            for (int j = tid; j < n; j += NTHR) {
                u64 k = kp[j];
                if (!k) continue;
                if (k == pick) { kp[j] = 0ULL; continue; }
                u32 pk2 = ~(u32)k;
                float4 c4 = dec[pk2 >> 8];
                float shift2 = __fmul_rn((float)((pk2 & 255u) + 1), off);
                float x1 = __fadd_rn(c4.x, shift2), y1 = __fadd_rn(c4.y, shift2);
                float x2 = __fadd_rn(c4.z, shift2), y2 = __fadd_rn(c4.w, shift2);
                float ix1 = fmaxf(x1, px1), iy1 = fmaxf(y1, py1);
                float ix2 = fminf(x2, px2), iy2 = fminf(y2, py2);
                float inter = __fmul_rn(fmaxf(__fsub_rn(ix2, ix1), 0.f),
                                        fmaxf(__fsub_rn(iy2, iy1), 0.f));
                float ar  = __fmul_rn(__fsub_rn(x2, x1), __fsub_rn(y2, y1));
                float iou = __fdiv_rn(inter, __fsub_rn(__fadd_rn(ar, pare), inter));
                if (iou > NMS_THRESH) kp[j] = 0ULL;
            }
            __syncthreads();
        }
    }

    /* restore zero state for next graph replay */
    __syncthreads();
    for (int l = tid; l < 256; l += NTHR) g_lmax[b * 256 + l] = 0ULL;
    if (tid == 0) { g_count[b] = 0; g_maxbits[b] = 0u; g_minbits[b] = 0u; }
}

extern "C" void kernel_launch(void* const* d_in, const int* in_sizes, int n_in,
                              void* d_out, int out_size) {
    const float *deltas = nullptr, *obj = nullptr, *priors = nullptr;
    for (int i = 0; i < n_in; i++) {
        if      (in_sizes[i] == BATCH * NPRI * 4)    deltas = (const float*)d_in[i];
        else if (in_sizes[i] == BATCH * NPRI * NCLS) obj    = (const float*)d_in[i];
        else if (in_sizes[i] == NPRI * 4)            priors = (const float*)d_in[i];
    }
    cudaFuncSetAttribute(nms_kernel, cudaFuncAttributeMaxDynamicSharedMemorySize,
                         (int)sizeof(Sm));
    dim3 g(NPRI / 8, BATCH);
    stage_a<<<g, 256>>>(deltas, obj, priors);
    nms_kernel<<<BATCH, NTHR, sizeof(Sm)>>>((float*)d_out);
}